// round 6
// baseline (speedup 1.0000x reference)
#include <cuda_runtime.h>

// MLP 64->4->8->8->32, sigmoid each layer, fp32, batch 1M (384MB traffic).
// L1/MIO-pipe-bound. This revision:
//  - select-free 3-shuffle reduce-scatter for layer 0 (per-lane permuted W0
//    rows make the butterfly work without FSELs)
//  - W3 fragment + b3 hoisted into registers (loop-invariant; previously
//    re-read from smem every store iteration because regs were capped)
//  - psum exchange: conflict-free transposed scalar STS/LDS (bank = 2k+row)
//  - warp-local dataflow only: __syncwarp in the hot path
// launch_bounds(128,6): ~85 regs, 24 warps/SM.

#define TPB 128
#define PK 34                 // psum k-stride (words)
#define PSUM_WARP (16 * PK)   // floats per warp region = 544

__device__ __forceinline__ float sigmoidf_fast(float x) {
    return __fdividef(1.0f, 1.0f + __expf(-x));
}

__device__ __forceinline__ float dot4(float4 a, float4 b) {
    float s = a.x * b.x;
    s = fmaf(a.y, b.y, s);
    s = fmaf(a.z, b.z, s);
    s = fmaf(a.w, b.w, s);
    return s;
}

__global__ void __launch_bounds__(TPB, 6)
mlp_kernel(const float* __restrict__ x,
           const float* __restrict__ W0, const float* __restrict__ b0,
           const float* __restrict__ W1, const float* __restrict__ b1,
           const float* __restrict__ W2, const float* __restrict__ b2,
           const float* __restrict__ W3, const float* __restrict__ b3,
           float* __restrict__ out, int batch)
{
    __shared__ __align__(16) float psum[4 * PSUM_WARP];  // 8704 B
    __shared__ __align__(16) float h2s[TPB * 12];        // 6144 B
    __shared__ __align__(16) float sW1[32];
    __shared__ __align__(16) float sW2[64];
    __shared__ float sB1[8], sB2[8];

    const int tid  = threadIdx.x;
    const int lane = tid & 31;
    const int wid  = tid >> 5;

    // ---- cooperative weight load (small: W1, W2, b1, b2) ----
    if (tid < 64)       sW2[tid]       = W2[tid];
    else if (tid < 96)  sW1[tid - 64]  = W1[tid - 64];
    else if (tid < 104) sB1[tid - 96]  = b1[tid - 96];
    else if (tid < 112) sB2[tid - 104] = b2[tid - 104];
    __syncthreads();

    const int warpRow = (blockIdx.x * (TPB / 32) + wid) * 32;
    if (warpRow >= batch) return;          // whole-warp exit only

    // ---- W0 fragment in registers, rows PERMUTED per lane so the
    //      reduce-scatter butterfly needs no selects ----
    const int c   = lane & 15;
    const int b0i = lane & 1;
    const int b1i = (lane >> 1) & 1;
    const int j0 = 2 * b1i + b0i;
    const int j1 = 2 * b1i + (b0i ^ 1);
    const int j2 = 2 * (b1i ^ 1) + b0i;
    const int j3 = 2 * (b1i ^ 1) + (b0i ^ 1);
    const float4 w0f0 = __ldg((const float4*)(W0 + j0 * 64) + c);
    const float4 w0f1 = __ldg((const float4*)(W0 + j1 * 64) + c);
    const float4 w0f2 = __ldg((const float4*)(W0 + j2 * 64) + c);
    const float4 w0f3 = __ldg((const float4*)(W0 + j3 * 64) + c);
    const float4 b0v  = __ldg((const float4*)b0);

    // ---- W3 fragment + bias in registers (loop-invariant for layer 3) ----
    const int c4 = lane & 7;
    float4 w3a[4], w3b[4];
    #pragma unroll
    for (int kk = 0; kk < 4; ++kk) {
        w3a[kk] = __ldg((const float4*)(W3 + (c4 * 4 + kk) * 8));
        w3b[kk] = __ldg((const float4*)(W3 + (c4 * 4 + kk) * 8 + 4));
    }
    const float4 b3v = __ldg((const float4*)b3 + c4);

    const float4* __restrict__ xw = (const float4*)x + (size_t)warpRow * 16;
    const int lim4 = batch * 16 - warpRow * 16;    // remaining float4 of x

    const int pw = wid * PSUM_WARP;                // this warp's psum base
    // store slot: [k = lane&15][row = 2i + (lane>>4)], bank = 2k+row distinct
    const int sbase = pw + (lane & 15) * PK + (lane >> 4);

    // ---- layer 0 in load domain: 4 dots + 3 shuffles + 1 STS per iter ----
    #pragma unroll
    for (int i = 0; i < 16; ++i) {
        int gi = i * 32 + lane;
        float4 v = make_float4(0.f, 0.f, 0.f, 0.f);
        if (gi < lim4) v = __ldcs(&xw[gi]);        // coalesced LDG.128
        float p0 = dot4(v, w0f0);
        float p1 = dot4(v, w0f1);
        float p2 = dot4(v, w0f2);
        float p3 = dot4(v, w0f3);
        float u0 = p0 + __shfl_xor_sync(0xffffffffu, p1, 1);
        float u1 = p2 + __shfl_xor_sync(0xffffffffu, p3, 1);
        float r4 = u0 + __shfl_xor_sync(0xffffffffu, u1, 2);
        psum[sbase + 2 * i] = r4;                  // conflict-free scalar STS
    }
    __syncwarp();

    // ---- per-row: finish layer 0 (16 scalar LDS, conflict-free) ----
    float vk[16];
    #pragma unroll
    for (int k = 0; k < 16; ++k) vk[k] = psum[pw + k * PK + lane];
    float4 h0;
    h0.x = sigmoidf_fast(((vk[0] + vk[4]) + (vk[8]  + vk[12])) + b0v.x);
    h0.y = sigmoidf_fast(((vk[1] + vk[5]) + (vk[9]  + vk[13])) + b0v.y);
    h0.z = sigmoidf_fast(((vk[2] + vk[6]) + (vk[10] + vk[14])) + b0v.z);
    h0.w = sigmoidf_fast(((vk[3] + vk[7]) + (vk[11] + vk[15])) + b0v.w);

    // ---- layer 1: 4 -> 8 (broadcast LDS) ----
    float h1[8];
    #pragma unroll
    for (int j = 0; j < 8; ++j) {
        float4 w = *(const float4*)&sW1[j * 4];
        h1[j] = sigmoidf_fast(sB1[j] + dot4(h0, w));
    }
    float4 ha = make_float4(h1[0], h1[1], h1[2], h1[3]);
    float4 hb = make_float4(h1[4], h1[5], h1[6], h1[7]);

    // ---- layer 2: 8 -> 8 ----
    float h2[8];
    #pragma unroll
    for (int j = 0; j < 8; ++j) {
        float4 wa = *(const float4*)&sW2[j * 8];
        float4 wb = *(const float4*)&sW2[j * 8 + 4];
        h2[j] = sigmoidf_fast(sB2[j] + dot4(ha, wa) + dot4(hb, wb));
    }

    *(float4*)&h2s[tid * 12]     = make_float4(h2[0], h2[1], h2[2], h2[3]);
    *(float4*)&h2s[tid * 12 + 4] = make_float4(h2[4], h2[5], h2[6], h2[7]);
    __syncwarp();

    // ---- layer 3 in coalesced store domain (weights in regs) ----
    float4* __restrict__ ow = (float4*)out + (size_t)warpRow * 8;
    const int olim = batch * 8 - warpRow * 8;
    const int prow = wid * 32;
    #pragma unroll
    for (int k = 0; k < 8; ++k) {
        int gi = k * 32 + lane;
        int rl = prow + (gi >> 3);                 // local row owning gi
        float4 ra = *(const float4*)&h2s[rl * 12];
        float4 rb = *(const float4*)&h2s[rl * 12 + 4];
        float o0 = sigmoidf_fast(b3v.x + dot4(ra, w3a[0]) + dot4(rb, w3b[0]));
        float o1 = sigmoidf_fast(b3v.y + dot4(ra, w3a[1]) + dot4(rb, w3b[1]));
        float o2 = sigmoidf_fast(b3v.z + dot4(ra, w3a[2]) + dot4(rb, w3b[2]));
        float o3 = sigmoidf_fast(b3v.w + dot4(ra, w3a[3]) + dot4(rb, w3b[3]));
        if (gi < olim)
            __stcs(&ow[gi], make_float4(o0, o1, o2, o3));
    }
}

extern "C" void kernel_launch(void* const* d_in, const int* in_sizes, int n_in,
                              void* d_out, int out_size)
{
    const float* x  = (const float*)d_in[0];
    const float* W0 = (const float*)d_in[1];
    const float* b0 = (const float*)d_in[2];
    const float* W1 = (const float*)d_in[3];
    const float* b1 = (const float*)d_in[4];
    const float* W2 = (const float*)d_in[5];
    const float* b2 = (const float*)d_in[6];
    const float* W3 = (const float*)d_in[7];
    const float* b3 = (const float*)d_in[8];
    float* out = (float*)d_out;

    int batch = in_sizes[0] / 64;
    int grid = (batch + TPB - 1) / TPB;
    mlp_kernel<<<grid, TPB>>>(x, W0, b0, W1, b1, W2, b2, W3, b3, out, batch);
}

// round 7
// speedup vs baseline: 1.2562x; 1.2562x over previous
#include <cuda_runtime.h>

// MLP 64->4->8->8->32, sigmoid each layer, fp32, batch 1M (384MB traffic).
// L1-pipe + latency bound; constraint learned R2/R6: need 8 blocks/SM.
//  - select-free 3-shuffle reduce-scatter for layer 0 (per-lane permuted
//    W0 rows; no FSELs), conflict-free transposed scalar psum exchange
//  - layers 1-2 per-row, W1/W2 broadcast from smem
//  - layer 3 in coalesced-store domain; W3 repacked (stride 20) in smem,
//    explicitly loaded to registers AFTER w0f/vk die so it can stay hoisted
//  - unguarded fast path (batch%32 rows handled by scalar tail path)
// launch_bounds(128,8): 64 regs, 32 warps/SM.

#define TPB 128
#define PK 34                 // psum k-stride (words)
#define PSUM_WARP (16 * PK)   // floats per warp region = 544

__device__ __forceinline__ float sigmoidf_fast(float x) {
    return __fdividef(1.0f, 1.0f + __expf(-x));
}

__device__ __forceinline__ float dot4(float4 a, float4 b) {
    float s = a.x * b.x;
    s = fmaf(a.y, b.y, s);
    s = fmaf(a.z, b.z, s);
    s = fmaf(a.w, b.w, s);
    return s;
}

__global__ void __launch_bounds__(TPB, 8)
mlp_kernel(const float* __restrict__ x,
           const float* __restrict__ W0, const float* __restrict__ b0,
           const float* __restrict__ W1, const float* __restrict__ b1,
           const float* __restrict__ W2, const float* __restrict__ b2,
           const float* __restrict__ W3, const float* __restrict__ b3,
           float* __restrict__ out, int batch)
{
    __shared__ __align__(16) float psum[4 * PSUM_WARP];  // 8704 B
    __shared__ __align__(16) float h2s[TPB * 12];        // 6144 B
    __shared__ __align__(16) float sW1[32];
    __shared__ __align__(16) float sW2[64];
    __shared__ __align__(16) float sW3p[32 * 20];        // repacked, stride 20
    __shared__ __align__(16) float sB0[4];
    __shared__ float sB1[8], sB2[8], sB3[32];

    const int tid  = threadIdx.x;
    const int lane = tid & 31;
    const int wid  = tid >> 5;

    // ---- cooperative weight load ----
    if (tid < 64)       sW2[tid]       = W2[tid];
    else if (tid < 96)  sW1[tid - 64]  = W1[tid - 64];
    else if (tid < 104) sB1[tid - 96]  = b1[tid - 96];
    else if (tid < 112) sB2[tid - 104] = b2[tid - 104];
    else if (tid < 116) sB0[tid - 112] = b0[tid - 112];
    if (tid < 32) {
        sB3[tid] = b3[tid];
        // W3 row j -> repacked row (j&3)*8 + (j>>2), stride 20 words
        int rp = (tid & 3) * 8 + (tid >> 2);
        #pragma unroll
        for (int k = 0; k < 8; ++k) sW3p[rp * 20 + k] = W3[tid * 8 + k];
    }
    __syncthreads();

    const int warpRow = (blockIdx.x * (TPB / 32) + wid) * 32;
    if (warpRow >= batch) return;          // whole-warp exit only

    if (warpRow + 32 <= batch) {
        // ===================== fast path: full warp =====================
        // W0 fragment in regs, rows PERMUTED per lane -> select-free butterfly
        const int c   = lane & 15;
        const int b0i = lane & 1;
        const int b1i = (lane >> 1) & 1;
        const float4 w0f0 = __ldg((const float4*)(W0 + (2*b1i +  b0i     ) * 64) + c);
        const float4 w0f1 = __ldg((const float4*)(W0 + (2*b1i + (b0i ^ 1)) * 64) + c);
        const float4 w0f2 = __ldg((const float4*)(W0 + (2*(b1i^1) +  b0i     ) * 64) + c);
        const float4 w0f3 = __ldg((const float4*)(W0 + (2*(b1i^1) + (b0i ^ 1)) * 64) + c);

        const float4* __restrict__ xw = (const float4*)x + (size_t)warpRow * 16;
        const int pw = wid * PSUM_WARP;
        // store slot: [k = lane&15][row = 2i + (lane>>4)], bank = 2k+row
        const int sbase = pw + (lane & 15) * PK + (lane >> 4);

        // ---- layer 0: 4 dots + 3 shuffles + 1 STS per iter, no selects ----
        #pragma unroll
        for (int i = 0; i < 16; ++i) {
            float4 v = __ldcs(&xw[i * 32 + lane]);   // coalesced LDG.128
            float p0 = dot4(v, w0f0);
            float p1 = dot4(v, w0f1);
            float p2 = dot4(v, w0f2);
            float p3 = dot4(v, w0f3);
            float u0 = p0 + __shfl_xor_sync(0xffffffffu, p1, 1);
            float u1 = p2 + __shfl_xor_sync(0xffffffffu, p3, 1);
            float r4 = u0 + __shfl_xor_sync(0xffffffffu, u1, 2);
            psum[sbase + 2 * i] = r4;                // conflict-free STS
        }
        __syncwarp();

        // ---- per-row: finish layer 0 (16 scalar LDS, conflict-free) ----
        float vk[16];
        #pragma unroll
        for (int k = 0; k < 16; ++k) vk[k] = psum[pw + k * PK + lane];
        float4 h0;
        h0.x = sigmoidf_fast(((vk[0] + vk[4]) + (vk[8]  + vk[12])) + sB0[0]);
        h0.y = sigmoidf_fast(((vk[1] + vk[5]) + (vk[9]  + vk[13])) + sB0[1]);
        h0.z = sigmoidf_fast(((vk[2] + vk[6]) + (vk[10] + vk[14])) + sB0[2]);
        h0.w = sigmoidf_fast(((vk[3] + vk[7]) + (vk[11] + vk[15])) + sB0[3]);

        // ---- layer 1: 4 -> 8 (broadcast LDS) ----
        float h1[8];
        #pragma unroll
        for (int j = 0; j < 8; ++j) {
            float4 w = *(const float4*)&sW1[j * 4];
            h1[j] = sigmoidf_fast(sB1[j] + dot4(h0, w));
        }
        float4 ha = make_float4(h1[0], h1[1], h1[2], h1[3]);
        float4 hb = make_float4(h1[4], h1[5], h1[6], h1[7]);

        // ---- layer 2: 8 -> 8 ----
        float h2[8];
        #pragma unroll
        for (int j = 0; j < 8; ++j) {
            float4 wa = *(const float4*)&sW2[j * 8];
            float4 wb = *(const float4*)&sW2[j * 8 + 4];
            h2[j] = sigmoidf_fast(sB2[j] + dot4(ha, wa) + dot4(hb, wb));
        }

        *(float4*)&h2s[tid * 12]     = make_float4(h2[0], h2[1], h2[2], h2[3]);
        *(float4*)&h2s[tid * 12 + 4] = make_float4(h2[4], h2[5], h2[6], h2[7]);
        __syncwarp();

        // ---- layer 3: load W3 fragment into regs NOW (w0f/vk dead) ----
        const int c4 = lane & 7;
        float4 w3a[4], w3b[4], b3q;
        #pragma unroll
        for (int kk = 0; kk < 4; ++kk) {
            int rp = kk * 8 + c4;
            w3a[kk] = *(const float4*)&sW3p[rp * 20];
            w3b[kk] = *(const float4*)&sW3p[rp * 20 + 4];
        }
        b3q = make_float4(sB3[c4 * 4], sB3[c4 * 4 + 1],
                          sB3[c4 * 4 + 2], sB3[c4 * 4 + 3]);

        float4* __restrict__ ow = (float4*)out + (size_t)warpRow * 8;
        const int prow = wid * 32;
        #pragma unroll
        for (int k = 0; k < 8; ++k) {
            int gi = k * 32 + lane;
            int rl = prow + (gi >> 3);               // local row owning gi
            float4 ra = *(const float4*)&h2s[rl * 12];
            float4 rb = *(const float4*)&h2s[rl * 12 + 4];
            float o0 = sigmoidf_fast(b3q.x + dot4(ra, w3a[0]) + dot4(rb, w3b[0]));
            float o1 = sigmoidf_fast(b3q.y + dot4(ra, w3a[1]) + dot4(rb, w3b[1]));
            float o2 = sigmoidf_fast(b3q.z + dot4(ra, w3a[2]) + dot4(rb, w3b[2]));
            float o3 = sigmoidf_fast(b3q.w + dot4(ra, w3a[3]) + dot4(rb, w3b[3]));
            __stcs(&ow[gi], make_float4(o0, o1, o2, o3));
        }
    } else {
        // ============== tail path: per-row scalar (rare) ==============
        const int row = warpRow + lane;
        if (row < batch) {
            const float* xr = x + (size_t)row * 64;
            float t0[4];
            #pragma unroll
            for (int j = 0; j < 4; ++j) {
                float s = b0[j];
                for (int k = 0; k < 64; ++k) s = fmaf(xr[k], W0[j * 64 + k], s);
                t0[j] = sigmoidf_fast(s);
            }
            float t1[8];
            #pragma unroll
            for (int j = 0; j < 8; ++j) {
                float s = sB1[j];
                for (int k = 0; k < 4; ++k) s = fmaf(t0[k], sW1[j * 4 + k], s);
                t1[j] = sigmoidf_fast(s);
            }
            float t2[8];
            #pragma unroll
            for (int j = 0; j < 8; ++j) {
                float s = sB2[j];
                for (int k = 0; k < 8; ++k) s = fmaf(t1[k], sW2[j * 8 + k], s);
                t2[j] = sigmoidf_fast(s);
            }
            float* orow = out + (size_t)row * 32;
            #pragma unroll
            for (int j = 0; j < 32; ++j) {
                float s = b3[j];
                for (int k = 0; k < 8; ++k) s = fmaf(t2[k], W3[j * 8 + k], s);
                orow[j] = sigmoidf_fast(s);
            }
        }
    }
}

extern "C" void kernel_launch(void* const* d_in, const int* in_sizes, int n_in,
                              void* d_out, int out_size)
{
    const float* x  = (const float*)d_in[0];
    const float* W0 = (const float*)d_in[1];
    const float* b0 = (const float*)d_in[2];
    const float* W1 = (const float*)d_in[3];
    const float* b1 = (const float*)d_in[4];
    const float* W2 = (const float*)d_in[5];
    const float* b2 = (const float*)d_in[6];
    const float* W3 = (const float*)d_in[7];
    const float* b3 = (const float*)d_in[8];
    float* out = (float*)d_out;

    int batch = in_sizes[0] / 64;
    int grid = (batch + TPB - 1) / TPB;
    mlp_kernel<<<grid, TPB>>>(x, W0, b0, W1, b1, W2, b2, W3, b3, out, batch);
}

// round 8
// speedup vs baseline: 1.2619x; 1.0046x over previous
#include <cuda_runtime.h>
#include <cstdint>

// MLP 64->4->8->8->32, sigmoid each layer, fp32, batch 1M (384MB traffic).
// Balanced (L1/DRAM/issue all ~65%) -> cut total issue slots + hottest pipe:
//  - hidden-layer sigmoid via tanh.approx.f32 (1 MUFU, 3 instr)
//  - layer 3 with fma.rn.f32x2: output-pairs packed, W3 interleaved in smem
//    (stride 44: conflict-free + 16B aligned) hoisted to packed registers
//  - select-free 3-shuffle reduce-scatter layer 0, conflict-free psum
//  - warp-local dataflow, 8 blocks/SM (learned R2/R6: occupancy is binding)

#define TPB 128
#define PK 34                 // psum k-stride (words)
#define PSUM_WARP (16 * PK)   // floats per warp region = 544
#define W3Q_STRIDE 44         // words per c4 group in sW3q (aligned, no-conflict)

__device__ __forceinline__ float sigmoidf_fast(float x) {   // output layer
    return __fdividef(1.0f, 1.0f + __expf(-x));
}
__device__ __forceinline__ float sigmoid_h(float x) {       // hidden layers
    float t;
    asm("tanh.approx.f32 %0, %1;" : "=f"(t) : "f"(0.5f * x));
    return fmaf(0.5f, t, 0.5f);
}

__device__ __forceinline__ float dot4(float4 a, float4 b) {
    float s = a.x * b.x;
    s = fmaf(a.y, b.y, s);
    s = fmaf(a.z, b.z, s);
    s = fmaf(a.w, b.w, s);
    return s;
}

__device__ __forceinline__ uint64_t pk2(float lo, float hi) {
    uint64_t r;
    asm("mov.b64 %0, {%1, %2};" : "=l"(r) : "f"(lo), "f"(hi));
    return r;
}
__device__ __forceinline__ void upk2(uint64_t v, float& lo, float& hi) {
    asm("mov.b64 {%0, %1}, %2;" : "=f"(lo), "=f"(hi) : "l"(v));
}
__device__ __forceinline__ uint64_t fma2(uint64_t a, uint64_t b, uint64_t c) {
    uint64_t d;
    asm("fma.rn.f32x2 %0, %1, %2, %3;" : "=l"(d) : "l"(a), "l"(b), "l"(c));
    return d;
}

__global__ void __launch_bounds__(TPB, 8)
mlp_kernel(const float* __restrict__ x,
           const float* __restrict__ W0, const float* __restrict__ b0,
           const float* __restrict__ W1, const float* __restrict__ b1,
           const float* __restrict__ W2, const float* __restrict__ b2,
           const float* __restrict__ W3, const float* __restrict__ b3,
           float* __restrict__ out, int batch)
{
    __shared__ __align__(16) float psum[4 * PSUM_WARP];   // 8704 B
    __shared__ __align__(16) float h2s[TPB * 12];         // 6144 B
    __shared__ __align__(16) float sW1[32];
    __shared__ __align__(16) float sW2[64];
    __shared__ __align__(16) float sW3q[8 * W3Q_STRIDE];  // interleaved W3
    __shared__ __align__(16) float sB0[4];
    __shared__ float sB1[8], sB2[8];

    const int tid  = threadIdx.x;
    const int lane = tid & 31;
    const int wid  = tid >> 5;

    // ---- cooperative weight load ----
    if (tid < 64)       sW2[tid]       = W2[tid];
    else if (tid < 96)  sW1[tid - 64]  = W1[tid - 64];
    else if (tid < 104) sB1[tid - 96]  = b1[tid - 96];
    else if (tid < 112) sB2[tid - 104] = b2[tid - 104];
    else if (tid < 116) sB0[tid - 112] = b0[tid - 112];
    if (tid < 32) {
        // W3 output j, comp c -> sW3q[(j>>2)*44 + c*4 + (j&3)]
        #pragma unroll
        for (int cc = 0; cc < 8; ++cc)
            sW3q[(tid >> 2) * W3Q_STRIDE + cc * 4 + (tid & 3)] = W3[tid * 8 + cc];
    }
    __syncthreads();

    const int warpRow = (blockIdx.x * (TPB / 32) + wid) * 32;
    if (warpRow >= batch) return;          // whole-warp exit only

    if (warpRow + 32 <= batch) {
        // ===================== fast path: full warp =====================
        // W0 fragment in regs, rows PERMUTED per lane -> select-free butterfly
        const int c   = lane & 15;
        const int b0i = lane & 1;
        const int b1i = (lane >> 1) & 1;
        const float4 w0f0 = __ldg((const float4*)(W0 + (2*b1i +  b0i     ) * 64) + c);
        const float4 w0f1 = __ldg((const float4*)(W0 + (2*b1i + (b0i ^ 1)) * 64) + c);
        const float4 w0f2 = __ldg((const float4*)(W0 + (2*(b1i^1) +  b0i     ) * 64) + c);
        const float4 w0f3 = __ldg((const float4*)(W0 + (2*(b1i^1) + (b0i ^ 1)) * 64) + c);

        const float4* __restrict__ xw = (const float4*)x + (size_t)warpRow * 16;
        const int pw = wid * PSUM_WARP;
        // store slot: [k = lane&15][row = 2i + (lane>>4)], bank = 2k+row
        const int sbase = pw + (lane & 15) * PK + (lane >> 4);

        // ---- layer 0: 4 dots + 3 shuffles + 1 STS per iter, no selects ----
        #pragma unroll
        for (int i = 0; i < 16; ++i) {
            float4 v = __ldcs(&xw[i * 32 + lane]);   // coalesced LDG.128
            float p0 = dot4(v, w0f0);
            float p1 = dot4(v, w0f1);
            float p2 = dot4(v, w0f2);
            float p3 = dot4(v, w0f3);
            float u0 = p0 + __shfl_xor_sync(0xffffffffu, p1, 1);
            float u1 = p2 + __shfl_xor_sync(0xffffffffu, p3, 1);
            float r4 = u0 + __shfl_xor_sync(0xffffffffu, u1, 2);
            psum[sbase + 2 * i] = r4;                // conflict-free STS
        }
        __syncwarp();

        // ---- per-row: finish layer 0 (16 scalar LDS, conflict-free) ----
        float vk[16];
        #pragma unroll
        for (int k = 0; k < 16; ++k) vk[k] = psum[pw + k * PK + lane];
        float4 h0;
        h0.x = sigmoid_h(((vk[0] + vk[4]) + (vk[8]  + vk[12])) + sB0[0]);
        h0.y = sigmoid_h(((vk[1] + vk[5]) + (vk[9]  + vk[13])) + sB0[1]);
        h0.z = sigmoid_h(((vk[2] + vk[6]) + (vk[10] + vk[14])) + sB0[2]);
        h0.w = sigmoid_h(((vk[3] + vk[7]) + (vk[11] + vk[15])) + sB0[3]);

        // ---- layer 1: 4 -> 8 (broadcast LDS) ----
        float h1[8];
        #pragma unroll
        for (int j = 0; j < 8; ++j) {
            float4 w = *(const float4*)&sW1[j * 4];
            h1[j] = sigmoid_h(sB1[j] + dot4(h0, w));
        }
        float4 ha = make_float4(h1[0], h1[1], h1[2], h1[3]);
        float4 hb = make_float4(h1[4], h1[5], h1[6], h1[7]);

        // ---- layer 2: 8 -> 8 ----
        float h2[8];
        #pragma unroll
        for (int j = 0; j < 8; ++j) {
            float4 wa = *(const float4*)&sW2[j * 8];
            float4 wb = *(const float4*)&sW2[j * 8 + 4];
            h2[j] = sigmoid_h(sB2[j] + dot4(ha, wa) + dot4(hb, wb));
        }

        *(float4*)&h2s[tid * 12]     = make_float4(h2[0], h2[1], h2[2], h2[3]);
        *(float4*)&h2s[tid * 12 + 4] = make_float4(h2[4], h2[5], h2[6], h2[7]);
        __syncwarp();

        // ---- layer 3: packed-output f32x2. Load interleaved W3 into
        //      packed registers now (w0f/vk dead). ----
        const int c4 = lane & 7;
        uint64_t wq01[8], wq23[8];
        #pragma unroll
        for (int cc = 0; cc < 8; ++cc) {
            float4 w = *(const float4*)&sW3q[c4 * W3Q_STRIDE + cc * 4];
            wq01[cc] = pk2(w.x, w.y);
            wq23[cc] = pk2(w.z, w.w);
        }
        const float4 b3v = __ldg((const float4*)b3 + c4);
        const uint64_t bp01 = pk2(b3v.x, b3v.y);
        const uint64_t bp23 = pk2(b3v.z, b3v.w);

        float4* __restrict__ ow = (float4*)out + (size_t)warpRow * 8;
        const int prow = wid * 32;
        #pragma unroll
        for (int k = 0; k < 8; ++k) {
            int gi = k * 32 + lane;
            int rl = prow + (gi >> 3);               // local row owning gi
            float4 ra = *(const float4*)&h2s[rl * 12];
            float4 rb = *(const float4*)&h2s[rl * 12 + 4];
            uint64_t a01 = bp01, a23 = bp23;
            uint64_t hd;
            hd = pk2(ra.x, ra.x); a01 = fma2(hd, wq01[0], a01); a23 = fma2(hd, wq23[0], a23);
            hd = pk2(ra.y, ra.y); a01 = fma2(hd, wq01[1], a01); a23 = fma2(hd, wq23[1], a23);
            hd = pk2(ra.z, ra.z); a01 = fma2(hd, wq01[2], a01); a23 = fma2(hd, wq23[2], a23);
            hd = pk2(ra.w, ra.w); a01 = fma2(hd, wq01[3], a01); a23 = fma2(hd, wq23[3], a23);
            hd = pk2(rb.x, rb.x); a01 = fma2(hd, wq01[4], a01); a23 = fma2(hd, wq23[4], a23);
            hd = pk2(rb.y, rb.y); a01 = fma2(hd, wq01[5], a01); a23 = fma2(hd, wq23[5], a23);
            hd = pk2(rb.z, rb.z); a01 = fma2(hd, wq01[6], a01); a23 = fma2(hd, wq23[6], a23);
            hd = pk2(rb.w, rb.w); a01 = fma2(hd, wq01[7], a01); a23 = fma2(hd, wq23[7], a23);
            float s0, s1, s2, s3;
            upk2(a01, s0, s1);
            upk2(a23, s2, s3);
            __stcs(&ow[gi], make_float4(sigmoidf_fast(s0), sigmoidf_fast(s1),
                                        sigmoidf_fast(s2), sigmoidf_fast(s3)));
        }
    } else {
        // ============== tail path: per-row scalar (rare) ==============
        const int row = warpRow + lane;
        if (row < batch) {
            const float* xr = x + (size_t)row * 64;
            float t0[4];
            #pragma unroll
            for (int j = 0; j < 4; ++j) {
                float s = b0[j];
                for (int k = 0; k < 64; ++k) s = fmaf(xr[k], W0[j * 64 + k], s);
                t0[j] = sigmoid_h(s);
            }
            float t1[8];
            #pragma unroll
            for (int j = 0; j < 8; ++j) {
                float s = sB1[j];
                for (int k = 0; k < 4; ++k) s = fmaf(t0[k], sW1[j * 4 + k], s);
                t1[j] = sigmoid_h(s);
            }
            float t2[8];
            #pragma unroll
            for (int j = 0; j < 8; ++j) {
                float s = sB2[j];
                for (int k = 0; k < 8; ++k) s = fmaf(t1[k], sW2[j * 8 + k], s);
                t2[j] = sigmoid_h(s);
            }
            float* orow = out + (size_t)row * 32;
            #pragma unroll
            for (int j = 0; j < 32; ++j) {
                float s = b3[j];
                for (int k = 0; k < 8; ++k) s = fmaf(t2[k], W3[j * 8 + k], s);
                orow[j] = sigmoidf_fast(s);
            }
        }
    }
}

extern "C" void kernel_launch(void* const* d_in, const int* in_sizes, int n_in,
                              void* d_out, int out_size)
{
    const float* x  = (const float*)d_in[0];
    const float* W0 = (const float*)d_in[1];
    const float* b0 = (const float*)d_in[2];
    const float* W1 = (const float*)d_in[3];
    const float* b1 = (const float*)d_in[4];
    const float* W2 = (const float*)d_in[5];
    const float* b2 = (const float*)d_in[6];
    const float* W3 = (const float*)d_in[7];
    const float* b3 = (const float*)d_in[8];
    float* out = (float*)d_out;

    int batch = in_sizes[0] / 64;
    int grid = (batch + TPB - 1) / TPB;
    mlp_kernel<<<grid, TPB>>>(x, W0, b0, W1, b1, W2, b2, W3, b3, out, batch);
}